// round 11
// baseline (speedup 1.0000x reference)
#include <cuda_runtime.h>
#include <cuda_fp16.h>

#define NU 200000
#define NI 100000
#define NN (NU + NI)          // nodes per pass
#define NN2 (2 * NN)          // merged node space (pos + neg)
#define EMAX_TOT 2500000
#define SCAN_ITEMS 2048
#define MAX_NB 512
#define NBUCK 256             // degree buckets per pass

// e-buffers in RANK space: row = 64 fp16 = 128B = one cache line.
__device__ __align__(256) uint4 g_e[5][NN2 * 8];
__device__ int    g_cnt[NN2];       // node space: degrees
__device__ int    g_cur[NN2];       // node space: fill cursors (rank offsets)
__device__ int    g_soff[NN2 + 1];  // rank space: CSR offsets (monotonic)
__device__ int    g_bsum[MAX_NB];
__device__ int    g_hist[2 * NBUCK];
__device__ int    g_hoff[2 * NBUCK];
__device__ int    g_perm[NN2];      // rank -> node
__device__ int    g_rank[NN2];      // node -> rank
__device__ float2 g_pl[2 * EMAX_TOT];   // {neighbor RANK (bits), norm}

__device__ __forceinline__ uint4 pack8(const float4& a, const float4& b) {
    __half2 h0 = __floats2half2_rn(a.x, a.y);
    __half2 h1 = __floats2half2_rn(a.z, a.w);
    __half2 h2 = __floats2half2_rn(b.x, b.y);
    __half2 h3 = __floats2half2_rn(b.z, b.w);
    uint4 r;
    r.x = *(unsigned*)&h0; r.y = *(unsigned*)&h1;
    r.z = *(unsigned*)&h2; r.w = *(unsigned*)&h3;
    return r;
}

__device__ __forceinline__ void unpack8(uint4 v, float4& a, float4& b) {
    __half2* hp = (__half2*)&v;
    float2 f0 = __half22float2(hp[0]);
    float2 f1 = __half22float2(hp[1]);
    float2 f2 = __half22float2(hp[2]);
    float2 f3 = __half22float2(hp[3]);
    a = make_float4(f0.x, f0.y, f1.x, f1.y);
    b = make_float4(f2.x, f2.y, f3.x, f3.y);
}

__global__ void k_count(const int* __restrict__ prow, const int* __restrict__ pcol,
                        const int* __restrict__ nrow, const int* __restrict__ ncol,
                        int Epos, int Etot) {
    int e = blockIdx.x * blockDim.x + threadIdx.x;
    if (e >= Etot) return;
    int r, c, base;
    if (e < Epos) { r = prow[e]; c = pcol[e]; base = 0; }
    else          { int f = e - Epos; r = nrow[f]; c = ncol[f]; base = NN; }
    atomicAdd(&g_cnt[base + r], 1);
    atomicAdd(&g_cnt[base + NU + c], 1);
}

// ---- Degree counting-sort (block-aggregated atomics) ----
__global__ void k_hist() {
    __shared__ int sh[2 * NBUCK];
    for (int b = threadIdx.x; b < 2 * NBUCK; b += blockDim.x) sh[b] = 0;
    __syncthreads();
    int i = blockIdx.x * blockDim.x + threadIdx.x;
    if (i < NN2) {
        int b = (i >= NN ? NBUCK : 0) + min(g_cnt[i], NBUCK - 1);
        atomicAdd(&sh[b], 1);
    }
    __syncthreads();
    for (int b = threadIdx.x; b < 2 * NBUCK; b += blockDim.x)
        if (sh[b]) atomicAdd(&g_hist[b], sh[b]);
}

__global__ void k_hscan() {
    __shared__ int sh[2 * NBUCK];
    int t = threadIdx.x;
    int v = g_hist[t];
    sh[t] = v;
    __syncthreads();
    for (int o = 1; o < 2 * NBUCK; o <<= 1) {
        int x = (t >= o) ? sh[t - o] : 0;
        __syncthreads();
        sh[t] += x;
        __syncthreads();
    }
    g_hoff[t] = sh[t] - v;   // pos buckets -> [0,NN), neg -> [NN,NN2)
}

__global__ void k_perm() {
    __shared__ int sh_cnt[2 * NBUCK];
    __shared__ int sh_base[2 * NBUCK];
    for (int b = threadIdx.x; b < 2 * NBUCK; b += blockDim.x) sh_cnt[b] = 0;
    __syncthreads();
    int i = blockIdx.x * blockDim.x + threadIdx.x;
    int b = -1;
    if (i < NN2) {
        b = (i >= NN ? NBUCK : 0) + min(g_cnt[i], NBUCK - 1);
        atomicAdd(&sh_cnt[b], 1);
    }
    __syncthreads();
    for (int bb = threadIdx.x; bb < 2 * NBUCK; bb += blockDim.x) {
        int c = sh_cnt[bb];
        sh_base[bb] = c ? atomicAdd(&g_hoff[bb], c) : 0;
        sh_cnt[bb] = 0;
    }
    __syncthreads();
    if (i < NN2) {
        int r = atomicAdd(&sh_cnt[b], 1);
        int p = sh_base[b] + r;
        g_perm[p] = i;
        g_rank[i] = p;
    }
}

// ---- Scan over PERM-ordered degrees -> rank-space CSR offsets ----
__global__ void k_scanA(int n) {
    __shared__ int wsum[16];
    int base = blockIdx.x * SCAN_ITEMS + threadIdx.x * 4;
    int v[4]; int s = 0;
#pragma unroll
    for (int j = 0; j < 4; j++) {
        int idx = base + j;
        v[j] = (idx < n) ? g_cnt[g_perm[idx]] : 0;
        s += v[j];
    }
    int lane = threadIdx.x & 31, warp = threadIdx.x >> 5;
    int incl = s;
#pragma unroll
    for (int o = 1; o < 32; o <<= 1) {
        int t = __shfl_up_sync(~0u, incl, o);
        if (lane >= o) incl += t;
    }
    if (lane == 31) wsum[warp] = incl;
    __syncthreads();
    if (warp == 0 && lane < 16) {
        int ws = wsum[lane];
#pragma unroll
        for (int o = 1; o < 16; o <<= 1) {
            int t = __shfl_up_sync(0xffffu, ws, o);
            if (lane >= o) ws += t;
        }
        wsum[lane] = ws;
    }
    __syncthreads();
    int excl = incl - s + (warp ? wsum[warp - 1] : 0);
    int run = excl;
#pragma unroll
    for (int j = 0; j < 4; j++) {
        int idx = base + j;
        if (idx < n) g_soff[idx] = run;
        run += v[j];
    }
    if (threadIdx.x == 0) g_bsum[blockIdx.x] = wsum[15];
}

__global__ void k_scanB(int nb) {
    __shared__ int sh[MAX_NB];
    int t = threadIdx.x;
    int v = (t < nb) ? g_bsum[t] : 0;
    sh[t] = v;
    __syncthreads();
    for (int o = 1; o < MAX_NB; o <<= 1) {
        int x = (t >= o) ? sh[t - o] : 0;
        __syncthreads();
        sh[t] += x;
        __syncthreads();
    }
    if (t < nb) g_bsum[t] = sh[t] - v;
}

__global__ void k_scanC(int n, int etot2) {
    int i = blockIdx.x * blockDim.x + threadIdx.x;
    if (i < n) {
        int o = g_soff[i] + g_bsum[i / SCAN_ITEMS];
        g_soff[i] = o;
        g_cur[g_perm[i]] = o;   // fill cursor, indexed by node
    }
    if (i == 0) g_soff[n] = etot2;   // sentinel
}

__global__ void k_fill(const int* __restrict__ prow, const int* __restrict__ pcol,
                       const float* __restrict__ pw,
                       const int* __restrict__ nrow, const int* __restrict__ ncol,
                       int Epos, int Etot) {
    int e = blockIdx.x * blockDim.x + threadIdx.x;
    if (e >= Etot) return;
    int r, c, base; float wv;
    if (e < Epos) { r = prow[e]; c = pcol[e]; base = 0; wv = pw[e]; }
    else          { int f = e - Epos; r = nrow[f]; c = ncol[f]; base = NN; wv = 1.f; }
    int gu = base + r, gi = base + NU + c;
    float nrm = rsqrtf((float)g_cnt[gu]) * rsqrtf((float)g_cnt[gi]) * wv;
    int ru = g_rank[gu], ri = g_rank[gi];
    int p0 = atomicAdd(&g_cur[gu], 1);
    g_pl[p0] = make_float2(__int_as_float(ri), nrm);
    int p1 = atomicAdd(&g_cur[gi], 1);
    g_pl[p1] = make_float2(__int_as_float(ru), nrm);
}

__device__ __forceinline__ const float4* node_emb(
    int node, const float4* up, const float4* ip,
    const float4* un, const float4* in_, int& li_out)
{
    int s = node >= NN;
    int n = s ? node - NN : node;
    const float4* e;
    int li;
    if (n < NU) { li = n;      e = s ? un : up; }
    else        { li = n - NU; e = s ? in_ : ip; }
    li_out = li;
    return e + (size_t)li * 16;
}

// e0[rank] = fp16(emb[perm[rank]]); active ranks only. 8 thr/node.
__global__ void k_init(const float4* __restrict__ up, const float4* __restrict__ ip,
                       const float4* __restrict__ un, const float4* __restrict__ in_,
                       int nbeg, int ncount) {
    int gid = blockIdx.x * blockDim.x + threadIdx.x;
    int g = nbeg + (gid >> 3);
    int t = gid & 7;
    if ((gid >> 3) >= ncount) return;
    if (g_soff[g + 1] == g_soff[g]) return;   // deg 0
    int node = g_perm[g];
    int li;
    const float4* src = node_emb(node, up, ip, un, in_, li);
    float4 a = __ldg(src + t * 2);
    float4 b = __ldg(src + t * 2 + 1);
    g_e[0][g * 8 + t] = pack8(a, b);
}

// Gather: ONE NODE PER WARP. Lane owns one half2 (columns 2L,2L+1).
// Row LDG.32 = exactly one 128B line per instr (no within-LDG replays).
// Payload: coalesced 32-entry batch preload + shfl.idx broadcast.
__global__ void k_gather(int k, int nbeg, int ncount) {
    int w = blockIdx.x * (blockDim.x >> 5) + (threadIdx.x >> 5);
    if (w >= ncount) return;
    int g = nbeg + w;
    int lane = threadIdx.x & 31;
    int beg = g_soff[g];
    int cnt = g_soff[g + 1] - beg;
    if (cnt == 0) return;

    const unsigned* __restrict__ src = (const unsigned*)g_e[k - 1];
    unsigned* __restrict__ dst = (unsigned*)g_e[k];

    unsigned sv = __ldg(src + g * 32 + lane);
    float2 acc = __half22float2(*reinterpret_cast<__half2*>(&sv));

    const float2* pl = g_pl + beg;
    for (int jb = 0; jb < cnt; jb += 32) {
        int m = min(32, cnt - jb);
        float2 pme = (lane < m) ? __ldg(pl + jb + lane) : make_float2(0.f, 0.f);
        int q = 0;
        for (; q + 4 <= m; q += 4) {
            unsigned wv[4]; float nn[4];
#pragma unroll
            for (int u = 0; u < 4; u++) {
                int idx = __shfl_sync(~0u, __float_as_int(pme.x), q + u);
                nn[u]   = __shfl_sync(~0u, pme.y, q + u);
                wv[u] = __ldg(src + idx * 32 + lane);
            }
#pragma unroll
            for (int u = 0; u < 4; u++) {
                float2 v = __half22float2(*reinterpret_cast<__half2*>(&wv[u]));
                acc.x = fmaf(v.x, nn[u], acc.x);
                acc.y = fmaf(v.y, nn[u], acc.y);
            }
        }
        for (; q < m; q++) {
            int idx = __shfl_sync(~0u, __float_as_int(pme.x), q);
            float n0 = __shfl_sync(~0u, pme.y, q);
            unsigned w0 = __ldg(src + idx * 32 + lane);
            float2 v = __half22float2(*reinterpret_cast<__half2*>(&w0));
            acc.x = fmaf(v.x, n0, acc.x);
            acc.y = fmaf(v.y, n0, acc.y);
        }
    }

    __half2 hv = __floats2half2_rn(acc.x, acc.y);
    dst[g * 32 + lane] = *reinterpret_cast<unsigned*>(&hv);
}

__global__ void k_final(const float4* __restrict__ up, const float4* __restrict__ ip,
                        const float4* __restrict__ un, const float4* __restrict__ in_,
                        float4* __restrict__ out, float inv, int nbeg, int ncount) {
    int gid = blockIdx.x * blockDim.x + threadIdx.x;
    int g = nbeg + (gid >> 3);
    int t = gid & 7;
    if ((gid >> 3) >= ncount) return;
    int node = g_perm[g];

    int li;
    const float4* esrc = node_emb(node, up, ip, un, in_, li);

    size_t obase;
    int s = node >= NN;
    int n = s ? node - NN : node;
    if (n < NU) obase = (size_t)(s ? (NU + NI) : 0) * 16 + (size_t)li * 16;
    else        obase = (size_t)(s ? (2 * NU + NI) : NU) * 16 + (size_t)li * 16;

    float4 s0 = __ldg(esrc + t * 2);
    float4 s1 = __ldg(esrc + t * 2 + 1);

    if (g_soff[g + 1] != g_soff[g]) {
#pragma unroll
        for (int k = 1; k <= 4; k++) {
            float4 a, b;
            unpack8(__ldg(&g_e[k][g * 8 + t]), a, b);
            s0.x += a.x; s0.y += a.y; s0.z += a.z; s0.w += a.w;
            s1.x += b.x; s1.y += b.y; s1.z += b.z; s1.w += b.w;
        }
        s0 = make_float4(s0.x * inv, s0.y * inv, s0.z * inv, s0.w * inv);
        s1 = make_float4(s1.x * inv, s1.y * inv, s1.z * inv, s1.w * inv);
    }
    out[obase + t * 2]     = s0;
    out[obase + t * 2 + 1] = s1;
}

// Restore zero-state invariant for next replay (globals start zeroed).
__global__ void k_cleanup() {
    int i = blockIdx.x * blockDim.x + threadIdx.x;
    if (i < NN2) g_cnt[i] = 0;
    if (i < 2 * NBUCK) g_hist[i] = 0;
}

extern "C" void kernel_launch(void* const* d_in, const int* in_sizes, int n_in,
                              void* d_out, int out_size) {
    const int*   ei  = (const int*)d_in[0];
    const int*   nei = (const int*)d_in[1];
    const float* ew  = (const float*)d_in[2];
    const float* up  = (const float*)d_in[3];
    const float* ip  = (const float*)d_in[4];
    const float* un  = (const float*)d_in[5];
    const float* inw = (const float*)d_in[6];
    float* out = (float*)d_out;

    const int Epos = in_sizes[0] / 2;
    const int Eneg = in_sizes[1] / 2;
    const int Etot = Epos + Eneg;
    const float inv = 1.0f / 5.0f;

    const int* prow = ei;
    const int* pcol = ei + Epos;
    const int* nrow = nei;
    const int* ncol = nei + Eneg;

    const int TB = 256;
    const int gNode = (NN2 + TB - 1) / TB;
    const int gE    = (Etot + TB - 1) / TB;
    const int NB    = (NN2 + SCAN_ITEMS - 1) / SCAN_ITEMS;
    const int gW    = (NN * 8 + TB - 1) / TB;    // 8 thr/node kernels
    const int gWarp = (NN + (TB / 32) - 1) / (TB / 32);   // 1 warp/node gather

    static cudaStream_t s2 = nullptr;
    static cudaEvent_t evFill = nullptr, evJoin = nullptr;
    if (!s2) {
        bool ok =
            (cudaStreamCreateWithFlags(&s2, cudaStreamNonBlocking) == cudaSuccess) &&
            (cudaEventCreateWithFlags(&evFill, cudaEventDisableTiming) == cudaSuccess) &&
            (cudaEventCreateWithFlags(&evJoin, cudaEventDisableTiming) == cudaSuccess);
        if (!ok) s2 = nullptr;
    }

    // Serial build chain: count -> sort(perm,rank) -> rank-ordered scan -> fill
    k_count<<<gE, TB>>>(prow, pcol, nrow, ncol, Epos, Etot);
    k_hist<<<gNode, TB>>>();
    k_hscan<<<1, 2 * NBUCK>>>();
    k_perm<<<gNode, TB>>>();
    k_scanA<<<NB, 512>>>(NN2);
    k_scanB<<<1, MAX_NB>>>(NB);
    k_scanC<<<gNode, TB>>>(NN2, 2 * Etot);
    k_fill<<<gE, TB>>>(prow, pcol, ew, nrow, ncol, Epos, Etot);

    if (s2) {
        cudaEventRecord(evFill, 0);
        cudaStreamWaitEvent(s2, evFill, 0);

        // Neg chain on s2: ranks [NN, 2NN)
        k_init<<<gW, TB, 0, s2>>>((const float4*)up, (const float4*)ip,
                                  (const float4*)un, (const float4*)inw, NN, NN);
        for (int l = 1; l <= 4; l++)
            k_gather<<<gWarp, TB, 0, s2>>>(l, NN, NN);
        k_final<<<gW, TB, 0, s2>>>((const float4*)up, (const float4*)ip,
                                   (const float4*)un, (const float4*)inw,
                                   (float4*)out, inv, NN, NN);
        cudaEventRecord(evJoin, s2);

        // Pos chain on main stream: ranks [0, NN)
        k_init<<<gW, TB>>>((const float4*)up, (const float4*)ip,
                           (const float4*)un, (const float4*)inw, 0, NN);
        for (int l = 1; l <= 4; l++)
            k_gather<<<gWarp, TB>>>(l, 0, NN);
        k_final<<<gW, TB>>>((const float4*)up, (const float4*)ip,
                            (const float4*)un, (const float4*)inw,
                            (float4*)out, inv, 0, NN);

        cudaStreamWaitEvent(0, evJoin, 0);
    } else {
        for (int s = 0; s < 2; s++) {
            int nbeg = s * NN;
            k_init<<<gW, TB>>>((const float4*)up, (const float4*)ip,
                               (const float4*)un, (const float4*)inw, nbeg, NN);
            for (int l = 1; l <= 4; l++)
                k_gather<<<gWarp, TB>>>(l, nbeg, NN);
            k_final<<<gW, TB>>>((const float4*)up, (const float4*)ip,
                                (const float4*)un, (const float4*)inw,
                                (float4*)out, inv, nbeg, NN);
        }
    }

    k_cleanup<<<gNode, TB>>>();
}

// round 12
// speedup vs baseline: 1.6225x; 1.6225x over previous
#include <cuda_runtime.h>
#include <cuda_fp16.h>

#define NU 200000
#define NI 100000
#define NN (NU + NI)          // nodes per pass
#define NN2 (2 * NN)          // merged node space (pos + neg)
#define EMAX_TOT 2500000
#define SCAN_ITEMS 2048
#define MAX_NB 512
#define NBUCK 256             // degree buckets per pass

// e-buffers in RANK space (perm order): row = 128B fp16 = 8 uint4.
// e[0..3] needed (e4 is fused into the output epilogue).
__device__ __align__(256) uint4 g_e[4][NN2 * 8];
__device__ int    g_cnt[NN2];       // node space: degrees
__device__ int    g_cur[NN2];       // node space: fill cursors (rank offsets)
__device__ int    g_soff[NN2 + 1];  // rank space: CSR offsets (monotonic)
__device__ int    g_bsum[MAX_NB];
__device__ int    g_hist[2 * NBUCK];
__device__ int    g_hoff[2 * NBUCK];
__device__ int    g_perm[NN2];      // rank -> node
__device__ int    g_rank[NN2];      // node -> rank
__device__ float2 g_pl[2 * EMAX_TOT];   // {neighbor RANK (bits), norm}

__device__ __forceinline__ uint4 pack8(const float4& a, const float4& b) {
    __half2 h0 = __floats2half2_rn(a.x, a.y);
    __half2 h1 = __floats2half2_rn(a.z, a.w);
    __half2 h2 = __floats2half2_rn(b.x, b.y);
    __half2 h3 = __floats2half2_rn(b.z, b.w);
    uint4 r;
    r.x = *(unsigned*)&h0; r.y = *(unsigned*)&h1;
    r.z = *(unsigned*)&h2; r.w = *(unsigned*)&h3;
    return r;
}

__device__ __forceinline__ void unpack8(uint4 v, float4& a, float4& b) {
    __half2* hp = (__half2*)&v;
    float2 f0 = __half22float2(hp[0]);
    float2 f1 = __half22float2(hp[1]);
    float2 f2 = __half22float2(hp[2]);
    float2 f3 = __half22float2(hp[3]);
    a = make_float4(f0.x, f0.y, f1.x, f1.y);
    b = make_float4(f2.x, f2.y, f3.x, f3.y);
}

__device__ __forceinline__ void fma8(float4& a0, float4& a1, uint4 w, float n) {
    float4 v0, v1;
    unpack8(w, v0, v1);
    a0.x = fmaf(v0.x, n, a0.x); a0.y = fmaf(v0.y, n, a0.y);
    a0.z = fmaf(v0.z, n, a0.z); a0.w = fmaf(v0.w, n, a0.w);
    a1.x = fmaf(v1.x, n, a1.x); a1.y = fmaf(v1.y, n, a1.y);
    a1.z = fmaf(v1.z, n, a1.z); a1.w = fmaf(v1.w, n, a1.w);
}

__global__ void k_count(const int* __restrict__ prow, const int* __restrict__ pcol,
                        const int* __restrict__ nrow, const int* __restrict__ ncol,
                        int Epos, int Etot) {
    int e = blockIdx.x * blockDim.x + threadIdx.x;
    if (e >= Etot) return;
    int r, c, base;
    if (e < Epos) { r = prow[e]; c = pcol[e]; base = 0; }
    else          { int f = e - Epos; r = nrow[f]; c = ncol[f]; base = NN; }
    atomicAdd(&g_cnt[base + r], 1);
    atomicAdd(&g_cnt[base + NU + c], 1);
}

// ---- Degree counting-sort (block-aggregated atomics) ----
__global__ void k_hist() {
    __shared__ int sh[2 * NBUCK];
    for (int b = threadIdx.x; b < 2 * NBUCK; b += blockDim.x) sh[b] = 0;
    __syncthreads();
    int i = blockIdx.x * blockDim.x + threadIdx.x;
    if (i < NN2) {
        int b = (i >= NN ? NBUCK : 0) + min(g_cnt[i], NBUCK - 1);
        atomicAdd(&sh[b], 1);
    }
    __syncthreads();
    for (int b = threadIdx.x; b < 2 * NBUCK; b += blockDim.x)
        if (sh[b]) atomicAdd(&g_hist[b], sh[b]);
}

__global__ void k_hscan() {
    __shared__ int sh[2 * NBUCK];
    int t = threadIdx.x;
    int v = g_hist[t];
    sh[t] = v;
    __syncthreads();
    for (int o = 1; o < 2 * NBUCK; o <<= 1) {
        int x = (t >= o) ? sh[t - o] : 0;
        __syncthreads();
        sh[t] += x;
        __syncthreads();
    }
    g_hoff[t] = sh[t] - v;   // pos buckets -> [0,NN), neg -> [NN,NN2)
}

__global__ void k_perm() {
    __shared__ int sh_cnt[2 * NBUCK];
    __shared__ int sh_base[2 * NBUCK];
    for (int b = threadIdx.x; b < 2 * NBUCK; b += blockDim.x) sh_cnt[b] = 0;
    __syncthreads();
    int i = blockIdx.x * blockDim.x + threadIdx.x;
    int b = -1;
    if (i < NN2) {
        b = (i >= NN ? NBUCK : 0) + min(g_cnt[i], NBUCK - 1);
        atomicAdd(&sh_cnt[b], 1);
    }
    __syncthreads();
    for (int bb = threadIdx.x; bb < 2 * NBUCK; bb += blockDim.x) {
        int c = sh_cnt[bb];
        sh_base[bb] = c ? atomicAdd(&g_hoff[bb], c) : 0;
        sh_cnt[bb] = 0;
    }
    __syncthreads();
    if (i < NN2) {
        int r = atomicAdd(&sh_cnt[b], 1);
        int p = sh_base[b] + r;
        g_perm[p] = i;
        g_rank[i] = p;
    }
}

// ---- Scan over PERM-ordered degrees -> rank-space CSR offsets ----
__global__ void k_scanA(int n) {
    __shared__ int wsum[16];
    int base = blockIdx.x * SCAN_ITEMS + threadIdx.x * 4;
    int v[4]; int s = 0;
#pragma unroll
    for (int j = 0; j < 4; j++) {
        int idx = base + j;
        v[j] = (idx < n) ? g_cnt[g_perm[idx]] : 0;
        s += v[j];
    }
    int lane = threadIdx.x & 31, warp = threadIdx.x >> 5;
    int incl = s;
#pragma unroll
    for (int o = 1; o < 32; o <<= 1) {
        int t = __shfl_up_sync(~0u, incl, o);
        if (lane >= o) incl += t;
    }
    if (lane == 31) wsum[warp] = incl;
    __syncthreads();
    if (warp == 0 && lane < 16) {
        int ws = wsum[lane];
#pragma unroll
        for (int o = 1; o < 16; o <<= 1) {
            int t = __shfl_up_sync(0xffffu, ws, o);
            if (lane >= o) ws += t;
        }
        wsum[lane] = ws;
    }
    __syncthreads();
    int excl = incl - s + (warp ? wsum[warp - 1] : 0);
    int run = excl;
#pragma unroll
    for (int j = 0; j < 4; j++) {
        int idx = base + j;
        if (idx < n) g_soff[idx] = run;
        run += v[j];
    }
    if (threadIdx.x == 0) g_bsum[blockIdx.x] = wsum[15];
}

__global__ void k_scanB(int nb) {
    __shared__ int sh[MAX_NB];
    int t = threadIdx.x;
    int v = (t < nb) ? g_bsum[t] : 0;
    sh[t] = v;
    __syncthreads();
    for (int o = 1; o < MAX_NB; o <<= 1) {
        int x = (t >= o) ? sh[t - o] : 0;
        __syncthreads();
        sh[t] += x;
        __syncthreads();
    }
    if (t < nb) g_bsum[t] = sh[t] - v;
}

__global__ void k_scanC(int n, int etot2) {
    int i = blockIdx.x * blockDim.x + threadIdx.x;
    if (i < n) {
        int o = g_soff[i] + g_bsum[i / SCAN_ITEMS];
        g_soff[i] = o;
        g_cur[g_perm[i]] = o;   // fill cursor, indexed by node
    }
    if (i == 0) g_soff[n] = etot2;   // sentinel
}

__global__ void k_fill(const int* __restrict__ prow, const int* __restrict__ pcol,
                       const float* __restrict__ pw,
                       const int* __restrict__ nrow, const int* __restrict__ ncol,
                       int Epos, int Etot) {
    int e = blockIdx.x * blockDim.x + threadIdx.x;
    if (e >= Etot) return;
    int r, c, base; float wv;
    if (e < Epos) { r = prow[e]; c = pcol[e]; base = 0; wv = pw[e]; }
    else          { int f = e - Epos; r = nrow[f]; c = ncol[f]; base = NN; wv = 1.f; }
    int gu = base + r, gi = base + NU + c;
    float nrm = rsqrtf((float)g_cnt[gu]) * rsqrtf((float)g_cnt[gi]) * wv;
    int ru = g_rank[gu], ri = g_rank[gi];
    int p0 = atomicAdd(&g_cur[gu], 1);
    g_pl[p0] = make_float2(__int_as_float(ri), nrm);
    int p1 = atomicAdd(&g_cur[gi], 1);
    g_pl[p1] = make_float2(__int_as_float(ru), nrm);
}

__device__ __forceinline__ const float4* node_emb(
    int node, const float4* up, const float4* ip,
    const float4* un, const float4* in_, int& li_out)
{
    int s = node >= NN;
    int n = s ? node - NN : node;
    const float4* e;
    int li;
    if (n < NU) { li = n;      e = s ? un : up; }
    else        { li = n - NU; e = s ? in_ : ip; }
    li_out = li;
    return e + (size_t)li * 16;
}

// e0[rank] = fp16(emb[perm[rank]]); active ranks only; BOTH passes.
__global__ void k_init(const float4* __restrict__ up, const float4* __restrict__ ip,
                       const float4* __restrict__ un, const float4* __restrict__ in_) {
    int gid = blockIdx.x * blockDim.x + threadIdx.x;
    int g = gid >> 3;
    int t = gid & 7;
    if (g >= NN2) return;
    if (g_soff[g + 1] == g_soff[g]) return;   // deg 0
    int node = g_perm[g];
    int li;
    const float4* src = node_emb(node, up, ip, un, in_, li);
    float4 a = __ldg(src + t * 2);
    float4 b = __ldg(src + t * 2 + 1);
    g_e[0][g * 8 + t] = pack8(a, b);
}

// Gather (layers 1..3): R10 body, rank space, 8 thr/node, 8/4/1 unroll.
__global__ void k_gather(int k, int nbeg, int ncount) {
    int gid = blockIdx.x * blockDim.x + threadIdx.x;
    int g = nbeg + (gid >> 3);
    int t = gid & 7;
    if ((gid >> 3) >= ncount) return;
    int beg = g_soff[g];
    int cnt = g_soff[g + 1] - beg;
    if (cnt == 0) return;

    const uint4* __restrict__ src = g_e[k - 1];
    uint4* __restrict__ dst = g_e[k];

    float4 acc0, acc1;
    unpack8(__ldg(src + g * 8 + t), acc0, acc1);

    const float2* pl = g_pl + beg;
    int j = 0;
    for (; j + 8 <= cnt; j += 8) {
        float2 p[8];
#pragma unroll
        for (int q = 0; q < 8; q++) p[q] = __ldg(pl + j + q);
        uint4 w[8];
#pragma unroll
        for (int q = 0; q < 8; q++)
            w[q] = __ldg(src + __float_as_int(p[q].x) * 8 + t);
#pragma unroll
        for (int q = 0; q < 8; q++) fma8(acc0, acc1, w[q], p[q].y);
    }
    if (j + 4 <= cnt) {
        float2 p[4];
#pragma unroll
        for (int q = 0; q < 4; q++) p[q] = __ldg(pl + j + q);
        uint4 w[4];
#pragma unroll
        for (int q = 0; q < 4; q++)
            w[q] = __ldg(src + __float_as_int(p[q].x) * 8 + t);
#pragma unroll
        for (int q = 0; q < 4; q++) fma8(acc0, acc1, w[q], p[q].y);
        j += 4;
    }
    for (; j < cnt; j++) {
        float2 p0 = __ldg(pl + j);
        uint4 w0 = __ldg(src + __float_as_int(p0.x) * 8 + t);
        fma8(acc0, acc1, w0, p0.y);
    }

    dst[g * 8 + t] = pack8(acc0, acc1);
}

// Layer 4 fused with the output epilogue:
// acc = e4 (fp32, pre-pack); out = (emb + e1 + e2 + e3 + acc) * inv.
// Deg-0 ranks: out = emb passthrough.
__global__ void k_gather_final(const float4* __restrict__ up, const float4* __restrict__ ip,
                               const float4* __restrict__ un, const float4* __restrict__ in_,
                               float4* __restrict__ out, float inv,
                               int nbeg, int ncount) {
    int gid = blockIdx.x * blockDim.x + threadIdx.x;
    int g = nbeg + (gid >> 3);
    int t = gid & 7;
    if ((gid >> 3) >= ncount) return;
    int beg = g_soff[g];
    int cnt = g_soff[g + 1] - beg;
    int node = g_perm[g];

    int li;
    const float4* esrc = node_emb(node, up, ip, un, in_, li);
    size_t obase;
    {
        int s = node >= NN;
        int n = s ? node - NN : node;
        if (n < NU) obase = (size_t)(s ? (NU + NI) : 0) * 16 + (size_t)li * 16;
        else        obase = (size_t)(s ? (2 * NU + NI) : NU) * 16 + (size_t)li * 16;
    }

    float4 e0a = __ldg(esrc + t * 2);
    float4 e0b = __ldg(esrc + t * 2 + 1);

    if (cnt == 0) {
        out[obase + t * 2]     = e0a;
        out[obase + t * 2 + 1] = e0b;
        return;
    }

    const uint4* __restrict__ src = g_e[3];

    float4 acc0, acc1;
    unpack8(__ldg(src + g * 8 + t), acc0, acc1);

    const float2* pl = g_pl + beg;
    int j = 0;
    for (; j + 8 <= cnt; j += 8) {
        float2 p[8];
#pragma unroll
        for (int q = 0; q < 8; q++) p[q] = __ldg(pl + j + q);
        uint4 w[8];
#pragma unroll
        for (int q = 0; q < 8; q++)
            w[q] = __ldg(src + __float_as_int(p[q].x) * 8 + t);
#pragma unroll
        for (int q = 0; q < 8; q++) fma8(acc0, acc1, w[q], p[q].y);
    }
    if (j + 4 <= cnt) {
        float2 p[4];
#pragma unroll
        for (int q = 0; q < 4; q++) p[q] = __ldg(pl + j + q);
        uint4 w[4];
#pragma unroll
        for (int q = 0; q < 4; q++)
            w[q] = __ldg(src + __float_as_int(p[q].x) * 8 + t);
#pragma unroll
        for (int q = 0; q < 4; q++) fma8(acc0, acc1, w[q], p[q].y);
        j += 4;
    }
    for (; j < cnt; j++) {
        float2 p0 = __ldg(pl + j);
        uint4 w0 = __ldg(src + __float_as_int(p0.x) * 8 + t);
        fma8(acc0, acc1, w0, p0.y);
    }

    // epilogue: sum emb + e1 + e2 + e3 + acc, scale
    float4 s0 = make_float4(e0a.x + acc0.x, e0a.y + acc0.y,
                            e0a.z + acc0.z, e0a.w + acc0.w);
    float4 s1 = make_float4(e0b.x + acc1.x, e0b.y + acc1.y,
                            e0b.z + acc1.z, e0b.w + acc1.w);
#pragma unroll
    for (int k = 1; k <= 3; k++) {
        float4 a, b;
        unpack8(__ldg(&g_e[k][g * 8 + t]), a, b);
        s0.x += a.x; s0.y += a.y; s0.z += a.z; s0.w += a.w;
        s1.x += b.x; s1.y += b.y; s1.z += b.z; s1.w += b.w;
    }
    out[obase + t * 2]     = make_float4(s0.x * inv, s0.y * inv, s0.z * inv, s0.w * inv);
    out[obase + t * 2 + 1] = make_float4(s1.x * inv, s1.y * inv, s1.z * inv, s1.w * inv);
}

// Restore zero-state invariant for next replay (globals start zeroed).
__global__ void k_cleanup() {
    int i = blockIdx.x * blockDim.x + threadIdx.x;
    if (i < NN2) g_cnt[i] = 0;
    if (i < 2 * NBUCK) g_hist[i] = 0;
}

extern "C" void kernel_launch(void* const* d_in, const int* in_sizes, int n_in,
                              void* d_out, int out_size) {
    const int*   ei  = (const int*)d_in[0];
    const int*   nei = (const int*)d_in[1];
    const float* ew  = (const float*)d_in[2];
    const float* up  = (const float*)d_in[3];
    const float* ip  = (const float*)d_in[4];
    const float* un  = (const float*)d_in[5];
    const float* inw = (const float*)d_in[6];
    float* out = (float*)d_out;

    const int Epos = in_sizes[0] / 2;
    const int Eneg = in_sizes[1] / 2;
    const int Etot = Epos + Eneg;
    const float inv = 1.0f / 5.0f;

    const int* prow = ei;
    const int* pcol = ei + Epos;
    const int* nrow = nei;
    const int* ncol = nei + Eneg;

    const int TB = 256;
    const int gNode = (NN2 + TB - 1) / TB;
    const int gE    = (Etot + TB - 1) / TB;
    const int NB    = (NN2 + SCAN_ITEMS - 1) / SCAN_ITEMS;
    const int gW    = (NN * 8 + TB - 1) / TB;    // per-pass rank range
    const int gW2   = (NN2 * 8 + TB - 1) / TB;   // all ranks (init)

    static cudaStream_t s2 = nullptr;
    static cudaEvent_t evC = nullptr, evInit = nullptr,
                       evFill = nullptr, evJoin = nullptr;
    if (!s2) {
        bool ok =
            (cudaStreamCreateWithFlags(&s2, cudaStreamNonBlocking) == cudaSuccess) &&
            (cudaEventCreateWithFlags(&evC, cudaEventDisableTiming) == cudaSuccess) &&
            (cudaEventCreateWithFlags(&evInit, cudaEventDisableTiming) == cudaSuccess) &&
            (cudaEventCreateWithFlags(&evFill, cudaEventDisableTiming) == cudaSuccess) &&
            (cudaEventCreateWithFlags(&evJoin, cudaEventDisableTiming) == cudaSuccess);
        if (!ok) s2 = nullptr;
    }

    // Build chain: count -> sort(perm,rank) -> rank-ordered scan
    k_count<<<gE, TB>>>(prow, pcol, nrow, ncol, Epos, Etot);
    k_hist<<<gNode, TB>>>();
    k_hscan<<<1, 2 * NBUCK>>>();
    k_perm<<<gNode, TB>>>();
    k_scanA<<<NB, 512>>>(NN2);
    k_scanB<<<1, MAX_NB>>>(NB);
    k_scanC<<<gNode, TB>>>(NN2, 2 * Etot);

    if (s2) {
        // Overlap init (s2) with fill (main) — disjoint outputs.
        cudaEventRecord(evC, 0);
        cudaStreamWaitEvent(s2, evC, 0);
        k_init<<<gW2, TB, 0, s2>>>((const float4*)up, (const float4*)ip,
                                   (const float4*)un, (const float4*)inw);
        cudaEventRecord(evInit, s2);

        k_fill<<<gE, TB>>>(prow, pcol, ew, nrow, ncol, Epos, Etot);
        cudaEventRecord(evFill, 0);
        cudaStreamWaitEvent(0, evInit, 0);

        // Neg chain on s2 (init done in-order on s2; wait for fill)
        cudaStreamWaitEvent(s2, evFill, 0);
        for (int l = 1; l <= 3; l++)
            k_gather<<<gW, TB, 0, s2>>>(l, NN, NN);
        k_gather_final<<<gW, TB, 0, s2>>>((const float4*)up, (const float4*)ip,
                                          (const float4*)un, (const float4*)inw,
                                          (float4*)out, inv, NN, NN);
        cudaEventRecord(evJoin, s2);

        // Pos chain on main stream
        for (int l = 1; l <= 3; l++)
            k_gather<<<gW, TB>>>(l, 0, NN);
        k_gather_final<<<gW, TB>>>((const float4*)up, (const float4*)ip,
                                   (const float4*)un, (const float4*)inw,
                                   (float4*)out, inv, 0, NN);

        cudaStreamWaitEvent(0, evJoin, 0);
    } else {
        k_fill<<<gE, TB>>>(prow, pcol, ew, nrow, ncol, Epos, Etot);
        k_init<<<gW2, TB>>>((const float4*)up, (const float4*)ip,
                            (const float4*)un, (const float4*)inw);
        for (int s = 0; s < 2; s++) {
            int nbeg = s * NN;
            for (int l = 1; l <= 3; l++)
                k_gather<<<gW, TB>>>(l, nbeg, NN);
            k_gather_final<<<gW, TB>>>((const float4*)up, (const float4*)ip,
                                       (const float4*)un, (const float4*)inw,
                                       (float4*)out, inv, nbeg, NN);
        }
    }

    k_cleanup<<<gNode, TB>>>();
}

// round 14
// speedup vs baseline: 1.8139x; 1.1180x over previous
#include <cuda_runtime.h>
#include <cuda_fp16.h>

#define NU 200000
#define NI 100000
#define NN (NU + NI)          // nodes per pass
#define NN2 (2 * NN)
#define EMAX_TOT 2500000
#define SCAN_ITEMS 2048
#define MAX_NB 512
#define NBUCK 256             // degree buckets per pass

// e-buffers in RANK space: row = 128B fp16 = 8 uint4. e[0..3]; e4 fused out.
__device__ __align__(256) uint4 g_e[4][NN2 * 8];
__device__ int    g_cnt[NN2];
__device__ int    g_cur[NN2];
__device__ int    g_soff[NN2 + 2];   // pos: [0..NN], neg: [NN+1..2NN+1] — disjoint
__device__ int    g_bsumP[MAX_NB];
__device__ int    g_bsumN[MAX_NB];
__device__ int    g_hist[2 * NBUCK];
__device__ int    g_hoff[2 * NBUCK];
__device__ int    g_perm[NN2];
__device__ int    g_rank[NN2];
__device__ float2 g_pl[2 * EMAX_TOT];   // {neighbor RANK (bits), norm}

__device__ __forceinline__ uint4 pack8(const float4& a, const float4& b) {
    __half2 h0 = __floats2half2_rn(a.x, a.y);
    __half2 h1 = __floats2half2_rn(a.z, a.w);
    __half2 h2 = __floats2half2_rn(b.x, b.y);
    __half2 h3 = __floats2half2_rn(b.z, b.w);
    uint4 r;
    r.x = *(unsigned*)&h0; r.y = *(unsigned*)&h1;
    r.z = *(unsigned*)&h2; r.w = *(unsigned*)&h3;
    return r;
}

__device__ __forceinline__ void unpack8(uint4 v, float4& a, float4& b) {
    __half2* hp = (__half2*)&v;
    float2 f0 = __half22float2(hp[0]);
    float2 f1 = __half22float2(hp[1]);
    float2 f2 = __half22float2(hp[2]);
    float2 f3 = __half22float2(hp[3]);
    a = make_float4(f0.x, f0.y, f1.x, f1.y);
    b = make_float4(f2.x, f2.y, f3.x, f3.y);
}

__device__ __forceinline__ void fma8(float4& a0, float4& a1, uint4 w, float n) {
    float4 v0, v1;
    unpack8(w, v0, v1);
    a0.x = fmaf(v0.x, n, a0.x); a0.y = fmaf(v0.y, n, a0.y);
    a0.z = fmaf(v0.z, n, a0.z); a0.w = fmaf(v0.w, n, a0.w);
    a1.x = fmaf(v1.x, n, a1.x); a1.y = fmaf(v1.y, n, a1.y);
    a1.z = fmaf(v1.z, n, a1.z); a1.w = fmaf(v1.w, n, a1.w);
}

// ---- Per-pass build kernels (nodeBase = 0 pos / NN neg) ----

__global__ void k_count(const int* __restrict__ row, const int* __restrict__ col,
                        int E, int nodeBase) {
    int e = blockIdx.x * blockDim.x + threadIdx.x;
    if (e >= E) return;
    atomicAdd(&g_cnt[nodeBase + row[e]], 1);
    atomicAdd(&g_cnt[nodeBase + NU + col[e]], 1);
}

__global__ void k_hist(int nodeBase, int bucketBase) {
    __shared__ int sh[NBUCK];
    for (int b = threadIdx.x; b < NBUCK; b += blockDim.x) sh[b] = 0;
    __syncthreads();
    int i = blockIdx.x * blockDim.x + threadIdx.x;
    if (i < NN) atomicAdd(&sh[min(g_cnt[nodeBase + i], NBUCK - 1)], 1);
    __syncthreads();
    for (int b = threadIdx.x; b < NBUCK; b += blockDim.x)
        if (sh[b]) atomicAdd(&g_hist[bucketBase + b], sh[b]);
}

__global__ void k_hscan(int bucketBase) {
    __shared__ int sh[NBUCK];
    int t = threadIdx.x;
    int v = g_hist[bucketBase + t];
    sh[t] = v;
    __syncthreads();
    for (int o = 1; o < NBUCK; o <<= 1) {
        int x = (t >= o) ? sh[t - o] : 0;
        __syncthreads();
        sh[t] += x;
        __syncthreads();
    }
    g_hoff[bucketBase + t] = sh[t] - v;
}

__global__ void k_perm(int nodeBase, int bucketBase) {
    __shared__ int sh_cnt[NBUCK];
    __shared__ int sh_base[NBUCK];
    for (int b = threadIdx.x; b < NBUCK; b += blockDim.x) sh_cnt[b] = 0;
    __syncthreads();
    int i = blockIdx.x * blockDim.x + threadIdx.x;
    int b = -1;
    if (i < NN) {
        b = min(g_cnt[nodeBase + i], NBUCK - 1);
        atomicAdd(&sh_cnt[b], 1);
    }
    __syncthreads();
    for (int bb = threadIdx.x; bb < NBUCK; bb += blockDim.x) {
        int c = sh_cnt[bb];
        sh_base[bb] = c ? atomicAdd(&g_hoff[bucketBase + bb], c) : 0;
        sh_cnt[bb] = 0;
    }
    __syncthreads();
    if (i < NN) {
        int r = atomicAdd(&sh_cnt[b], 1);
        int p = nodeBase + sh_base[b] + r;   // rankBase == nodeBase
        g_perm[p] = nodeBase + i;
        g_rank[nodeBase + i] = p;
    }
}

__global__ void k_scanA(int rankBase, int soffBase, int* __restrict__ bsum) {
    __shared__ int wsum[16];
    int base = blockIdx.x * SCAN_ITEMS + threadIdx.x * 4;
    int v[4]; int s = 0;
#pragma unroll
    for (int j = 0; j < 4; j++) {
        int idx = base + j;
        v[j] = (idx < NN) ? g_cnt[g_perm[rankBase + idx]] : 0;
        s += v[j];
    }
    int lane = threadIdx.x & 31, warp = threadIdx.x >> 5;
    int incl = s;
#pragma unroll
    for (int o = 1; o < 32; o <<= 1) {
        int t = __shfl_up_sync(~0u, incl, o);
        if (lane >= o) incl += t;
    }
    if (lane == 31) wsum[warp] = incl;
    __syncthreads();
    if (warp == 0 && lane < 16) {
        int ws = wsum[lane];
#pragma unroll
        for (int o = 1; o < 16; o <<= 1) {
            int t = __shfl_up_sync(0xffffu, ws, o);
            if (lane >= o) ws += t;
        }
        wsum[lane] = ws;
    }
    __syncthreads();
    int excl = incl - s + (warp ? wsum[warp - 1] : 0);
    int run = excl;
#pragma unroll
    for (int j = 0; j < 4; j++) {
        int idx = base + j;
        if (idx < NN) g_soff[soffBase + idx] = run;
        run += v[j];
    }
    if (threadIdx.x == 0) bsum[blockIdx.x] = wsum[15];
}

__global__ void k_scanB(int* __restrict__ bsum, int nb) {
    __shared__ int sh[MAX_NB];
    int t = threadIdx.x;
    int v = (t < nb) ? bsum[t] : 0;
    sh[t] = v;
    __syncthreads();
    for (int o = 1; o < MAX_NB; o <<= 1) {
        int x = (t >= o) ? sh[t - o] : 0;
        __syncthreads();
        sh[t] += x;
        __syncthreads();
    }
    if (t < nb) bsum[t] = sh[t] - v;
}

__global__ void k_scanC(int rankBase, int soffBase, const int* __restrict__ bsum,
                        int edgeBase, int edgeEnd) {
    int i = blockIdx.x * blockDim.x + threadIdx.x;
    if (i < NN) {
        int o = g_soff[soffBase + i] + bsum[i / SCAN_ITEMS] + edgeBase;
        g_soff[soffBase + i] = o;
        g_cur[g_perm[rankBase + i]] = o;
    }
    if (i == 0) g_soff[soffBase + NN] = edgeEnd;   // per-pass sentinel, disjoint slot
}

__global__ void k_fill(const int* __restrict__ row, const int* __restrict__ col,
                       const float* __restrict__ w, int E, int nodeBase) {
    int e = blockIdx.x * blockDim.x + threadIdx.x;
    if (e >= E) return;
    int r = row[e], c = col[e];
    float wv = w ? w[e] : 1.f;
    int gu = nodeBase + r, gi = nodeBase + NU + c;
    float nrm = rsqrtf((float)g_cnt[gu]) * rsqrtf((float)g_cnt[gi]) * wv;
    int ru = g_rank[gu], ri = g_rank[gi];
    int p0 = atomicAdd(&g_cur[gu], 1);
    g_pl[p0] = make_float2(__int_as_float(ri), nrm);
    int p1 = atomicAdd(&g_cur[gi], 1);
    g_pl[p1] = make_float2(__int_as_float(ru), nrm);
}

__device__ __forceinline__ const float4* node_emb(
    int node, const float4* up, const float4* ip,
    const float4* un, const float4* in_, int& li_out)
{
    int s = node >= NN;
    int n = s ? node - NN : node;
    const float4* e;
    int li;
    if (n < NU) { li = n;      e = s ? un : up; }
    else        { li = n - NU; e = s ? in_ : ip; }
    li_out = li;
    return e + (size_t)li * 16;
}

__global__ void k_init(const float4* __restrict__ up, const float4* __restrict__ ip,
                       const float4* __restrict__ un, const float4* __restrict__ in_,
                       int rankBase, int soffBase) {
    int gid = blockIdx.x * blockDim.x + threadIdx.x;
    int gl = gid >> 3;
    int t = gid & 7;
    if (gl >= NN) return;
    if (g_soff[soffBase + gl + 1] == g_soff[soffBase + gl]) return;   // deg 0
    int g = rankBase + gl;
    int node = g_perm[g];
    int li;
    const float4* src = node_emb(node, up, ip, un, in_, li);
    float4 a = __ldg(src + t * 2);
    float4 b = __ldg(src + t * 2 + 1);
    g_e[0][g * 8 + t] = pack8(a, b);
}

// Gather layers 1..3: rank space, 8 thr/node, 8/4/1 unroll.
__global__ void k_gather(int k, int rankBase, int soffBase) {
    int gid = blockIdx.x * blockDim.x + threadIdx.x;
    int gl = gid >> 3;
    int t = gid & 7;
    if (gl >= NN) return;
    int beg = g_soff[soffBase + gl];
    int cnt = g_soff[soffBase + gl + 1] - beg;
    if (cnt == 0) return;
    int g = rankBase + gl;

    const uint4* __restrict__ src = g_e[k - 1];
    uint4* __restrict__ dst = g_e[k];

    float4 acc0, acc1;
    unpack8(__ldg(src + g * 8 + t), acc0, acc1);

    const float2* pl = g_pl + beg;
    int j = 0;
    for (; j + 8 <= cnt; j += 8) {
        float2 p[8];
#pragma unroll
        for (int q = 0; q < 8; q++) p[q] = __ldg(pl + j + q);
        uint4 w[8];
#pragma unroll
        for (int q = 0; q < 8; q++)
            w[q] = __ldg(src + __float_as_int(p[q].x) * 8 + t);
#pragma unroll
        for (int q = 0; q < 8; q++) fma8(acc0, acc1, w[q], p[q].y);
    }
    if (j + 4 <= cnt) {
        float2 p[4];
#pragma unroll
        for (int q = 0; q < 4; q++) p[q] = __ldg(pl + j + q);
        uint4 w[4];
#pragma unroll
        for (int q = 0; q < 4; q++)
            w[q] = __ldg(src + __float_as_int(p[q].x) * 8 + t);
#pragma unroll
        for (int q = 0; q < 4; q++) fma8(acc0, acc1, w[q], p[q].y);
        j += 4;
    }
    for (; j < cnt; j++) {
        float2 p0 = __ldg(pl + j);
        uint4 w0 = __ldg(src + __float_as_int(p0.x) * 8 + t);
        fma8(acc0, acc1, w0, p0.y);
    }

    dst[g * 8 + t] = pack8(acc0, acc1);
}

// Layer 4 fused with output epilogue:
// acc = e4 (fp32 from e3 gather); out = (e0 + e1 + e2 + e3 + acc) * inv.
// Deg-0 ranks: out = exact fp32 emb passthrough.
__global__ void k_gather_final(const float4* __restrict__ up, const float4* __restrict__ ip,
                               const float4* __restrict__ un, const float4* __restrict__ in_,
                               float4* __restrict__ out, float inv,
                               int rankBase, int soffBase) {
    int gid = blockIdx.x * blockDim.x + threadIdx.x;
    int gl = gid >> 3;
    int t = gid & 7;
    if (gl >= NN) return;
    int beg = g_soff[soffBase + gl];
    int cnt = g_soff[soffBase + gl + 1] - beg;
    int g = rankBase + gl;
    int node = g_perm[g];

    size_t obase;
    {
        int s = node >= NN;
        int n = s ? node - NN : node;
        int li;
        if (n < NU) { li = n;      obase = (size_t)(s ? (NU + NI) : 0) * 16; }
        else        { li = n - NU; obase = (size_t)(s ? (2 * NU + NI) : NU) * 16; }
        obase += (size_t)li * 16;
    }

    if (cnt == 0) {
        int li;
        const float4* esrc = node_emb(node, up, ip, un, in_, li);
        out[obase + t * 2]     = __ldg(esrc + t * 2);
        out[obase + t * 2 + 1] = __ldg(esrc + t * 2 + 1);
        return;
    }

    const uint4* __restrict__ src = g_e[3];

    float4 acc0, acc1;
    unpack8(__ldg(src + g * 8 + t), acc0, acc1);   // = e3 self term -> e4 acc

    const float2* pl = g_pl + beg;
    int j = 0;
    for (; j + 8 <= cnt; j += 8) {
        float2 p[8];
#pragma unroll
        for (int q = 0; q < 8; q++) p[q] = __ldg(pl + j + q);
        uint4 w[8];
#pragma unroll
        for (int q = 0; q < 8; q++)
            w[q] = __ldg(src + __float_as_int(p[q].x) * 8 + t);
#pragma unroll
        for (int q = 0; q < 8; q++) fma8(acc0, acc1, w[q], p[q].y);
    }
    if (j + 4 <= cnt) {
        float2 p[4];
#pragma unroll
        for (int q = 0; q < 4; q++) p[q] = __ldg(pl + j + q);
        uint4 w[4];
#pragma unroll
        for (int q = 0; q < 4; q++)
            w[q] = __ldg(src + __float_as_int(p[q].x) * 8 + t);
#pragma unroll
        for (int q = 0; q < 4; q++) fma8(acc0, acc1, w[q], p[q].y);
        j += 4;
    }
    for (; j < cnt; j++) {
        float2 p0 = __ldg(pl + j);
        uint4 w0 = __ldg(src + __float_as_int(p0.x) * 8 + t);
        fma8(acc0, acc1, w0, p0.y);
    }

    // epilogue: out = (e0 + e1 + e2 + e3 + e4) * inv  [e4 = acc]
    float4 s0 = acc0, s1 = acc1;
#pragma unroll
    for (int k = 0; k <= 3; k++) {
        float4 a, b;
        unpack8(__ldg(&g_e[k][g * 8 + t]), a, b);
        s0.x += a.x; s0.y += a.y; s0.z += a.z; s0.w += a.w;
        s1.x += b.x; s1.y += b.y; s1.z += b.z; s1.w += b.w;
    }
    out[obase + t * 2]     = make_float4(s0.x * inv, s0.y * inv, s0.z * inv, s0.w * inv);
    out[obase + t * 2 + 1] = make_float4(s1.x * inv, s1.y * inv, s1.z * inv, s1.w * inv);
}

// Restore zero-state invariant for next replay.
__global__ void k_cleanup() {
    int i = blockIdx.x * blockDim.x + threadIdx.x;
    if (i < NN2) g_cnt[i] = 0;
    if (i < 2 * NBUCK) g_hist[i] = 0;
}

extern "C" void kernel_launch(void* const* d_in, const int* in_sizes, int n_in,
                              void* d_out, int out_size) {
    const int*   ei  = (const int*)d_in[0];
    const int*   nei = (const int*)d_in[1];
    const float* ew  = (const float*)d_in[2];
    const float* up  = (const float*)d_in[3];
    const float* ip  = (const float*)d_in[4];
    const float* un  = (const float*)d_in[5];
    const float* inw = (const float*)d_in[6];
    float* out = (float*)d_out;

    const int Epos = in_sizes[0] / 2;
    const int Eneg = in_sizes[1] / 2;
    const float inv = 1.0f / 5.0f;

    const int* prow = ei;
    const int* pcol = ei + Epos;
    const int* nrow = nei;
    const int* ncol = nei + Eneg;

    const int TB = 256;
    const int gNodeH = (NN + TB - 1) / TB;
    const int gNode2 = (NN2 + TB - 1) / TB;
    const int gEp    = (Epos + TB - 1) / TB;
    const int gEn    = (Eneg + TB - 1) / TB;
    const int NBh    = (NN + SCAN_ITEMS - 1) / SCAN_ITEMS;
    const int gW     = (NN * 8 + TB - 1) / TB;

    const int SOFF_P = 0;
    const int SOFF_N = NN + 1;

    static cudaStream_t s2 = nullptr;
    static cudaEvent_t evPF = nullptr, evJoin = nullptr;
    if (!s2) {
        bool ok =
            (cudaStreamCreateWithFlags(&s2, cudaStreamNonBlocking) == cudaSuccess) &&
            (cudaEventCreateWithFlags(&evPF, cudaEventDisableTiming) == cudaSuccess) &&
            (cudaEventCreateWithFlags(&evJoin, cudaEventDisableTiming) == cudaSuccess);
        if (!ok) s2 = nullptr;
    }

    if (s2) {
        // ---- POS pipeline on main stream ----
        k_count<<<gEp, TB>>>(prow, pcol, Epos, 0);
        k_hist<<<gNodeH, TB>>>(0, 0);
        k_hscan<<<1, NBUCK>>>(0);
        k_perm<<<gNodeH, TB>>>(0, 0);
        k_scanA<<<NBh, 512>>>(0, SOFF_P, g_bsumP);
        k_scanB<<<1, MAX_NB>>>(g_bsumP, NBh);
        k_scanC<<<gNodeH, TB>>>(0, SOFF_P, g_bsumP, 0, 2 * Epos);
        k_fill<<<gEp, TB>>>(prow, pcol, ew, Epos, 0);
        cudaEventRecord(evPF, 0);
        k_init<<<gW, TB>>>((const float4*)up, (const float4*)ip,
                           (const float4*)un, (const float4*)inw, 0, SOFF_P);

        // ---- NEG pipeline on s2 (fully disjoint arrays/slots) ----
        k_count<<<gEn, TB, 0, s2>>>(nrow, ncol, Eneg, NN);
        k_hist<<<gNodeH, TB, 0, s2>>>(NN, NBUCK);
        k_hscan<<<1, NBUCK, 0, s2>>>(NBUCK);
        k_perm<<<gNodeH, TB, 0, s2>>>(NN, NBUCK);
        k_scanA<<<NBh, 512, 0, s2>>>(NN, SOFF_N, g_bsumN);
        k_scanB<<<1, MAX_NB, 0, s2>>>(g_bsumN, NBh);
        k_scanC<<<gNodeH, TB, 0, s2>>>(NN, SOFF_N, g_bsumN, 2 * Epos, 2 * (Epos + Eneg));
        k_fill<<<gEn, TB, 0, s2>>>(nrow, ncol, nullptr, Eneg, NN);
        k_init<<<gW, TB, 0, s2>>>((const float4*)up, (const float4*)ip,
                                  (const float4*)un, (const float4*)inw, NN, SOFF_N);
        // cleanup after both fills (g_cnt/g_hist no longer read afterwards)
        cudaStreamWaitEvent(s2, evPF, 0);
        k_cleanup<<<gNode2, TB, 0, s2>>>();

        for (int l = 1; l <= 3; l++)
            k_gather<<<gW, TB, 0, s2>>>(l, NN, SOFF_N);
        k_gather_final<<<gW, TB, 0, s2>>>((const float4*)up, (const float4*)ip,
                                          (const float4*)un, (const float4*)inw,
                                          (float4*)out, inv, NN, SOFF_N);
        cudaEventRecord(evJoin, s2);

        // ---- POS gathers on main ----
        for (int l = 1; l <= 3; l++)
            k_gather<<<gW, TB>>>(l, 0, SOFF_P);
        k_gather_final<<<gW, TB>>>((const float4*)up, (const float4*)ip,
                                   (const float4*)un, (const float4*)inw,
                                   (float4*)out, inv, 0, SOFF_P);

        cudaStreamWaitEvent(0, evJoin, 0);
    } else {
        // Serial fallback
        k_count<<<gEp, TB>>>(prow, pcol, Epos, 0);
        k_count<<<gEn, TB>>>(nrow, ncol, Eneg, NN);
        k_hist<<<gNodeH, TB>>>(0, 0);
        k_hist<<<gNodeH, TB>>>(NN, NBUCK);
        k_hscan<<<1, NBUCK>>>(0);
        k_hscan<<<1, NBUCK>>>(NBUCK);
        k_perm<<<gNodeH, TB>>>(0, 0);
        k_perm<<<gNodeH, TB>>>(NN, NBUCK);
        k_scanA<<<NBh, 512>>>(0, SOFF_P, g_bsumP);
        k_scanA<<<NBh, 512>>>(NN, SOFF_N, g_bsumN);
        k_scanB<<<1, MAX_NB>>>(g_bsumP, NBh);
        k_scanB<<<1, MAX_NB>>>(g_bsumN, NBh);
        k_scanC<<<gNodeH, TB>>>(0, SOFF_P, g_bsumP, 0, 2 * Epos);
        k_scanC<<<gNodeH, TB>>>(NN, SOFF_N, g_bsumN, 2 * Epos, 2 * (Epos + Eneg));
        k_fill<<<gEp, TB>>>(prow, pcol, ew, Epos, 0);
        k_fill<<<gEn, TB>>>(nrow, ncol, nullptr, Eneg, NN);
        k_init<<<gW, TB>>>((const float4*)up, (const float4*)ip,
                           (const float4*)un, (const float4*)inw, 0, SOFF_P);
        k_init<<<gW, TB>>>((const float4*)up, (const float4*)ip,
                           (const float4*)un, (const float4*)inw, NN, SOFF_N);
        for (int s = 0; s < 2; s++) {
            int rb = s * NN, sb = s ? SOFF_N : SOFF_P;
            for (int l = 1; l <= 3; l++)
                k_gather<<<gW, TB>>>(l, rb, sb);
            k_gather_final<<<gW, TB>>>((const float4*)up, (const float4*)ip,
                                       (const float4*)un, (const float4*)inw,
                                       (float4*)out, inv, rb, sb);
        }
        k_cleanup<<<gNode2, TB>>>();
    }
}